// round 5
// baseline (speedup 1.0000x reference)
#include <cuda_runtime.h>
#include <cuda_bf16.h>
#include <math.h>
#include <stdint.h>

#define N 4096
#define D 768
#define TEMP_INV 20.0f
#define EPSN 1e-8f

#define BM 256
#define BN 128
#define BK 64
#define NCH (D / BK)          // 12 k-chunks
#define A_BYTES (BM * BK * 2) // 32 KB
#define B_BYTES (BN * BK * 2) // 16 KB
#define STAGE_BYTES (A_BYTES + B_BYTES)   // 48 KB
#define SMEM_DYN (3 * STAGE_BYTES)        // 144 KB

// ---------------------------------------------------------------------------
// Scratch (allocation-free: device globals)
// ---------------------------------------------------------------------------
__device__ __nv_bfloat16 g_a[(size_t)N * D];
__device__ __nv_bfloat16 g_b[(size_t)N * D];
__device__ float g_partial[(size_t)N * 32];
__device__ float g_diag[N];
__device__ float g_rowloss[N];
__device__ int   g_done;

// ---------------------------------------------------------------------------
__device__ __forceinline__ uint32_t smem_u32(const void* p) {
    uint32_t a;
    asm("{ .reg .u64 t; cvta.to.shared.u64 t, %1; cvt.u32.u64 %0, t; }" : "=r"(a) : "l"(p));
    return a;
}

#define CP_ASYNC16(dst, src) \
    asm volatile("cp.async.cg.shared.global [%0], [%1], 16;" :: "r"(dst), "l"(src) : "memory")
#define CP_COMMIT() asm volatile("cp.async.commit_group;" ::: "memory")
#define CP_WAIT(n)  asm volatile("cp.async.wait_group %0;" :: "n"(n) : "memory")

__device__ __forceinline__ void ldmx4(uint32_t* r, uint32_t addr) {
    asm volatile("ldmatrix.sync.aligned.m8n8.x4.shared.b16 {%0,%1,%2,%3}, [%4];"
                 : "=r"(r[0]), "=r"(r[1]), "=r"(r[2]), "=r"(r[3]) : "r"(addr));
}

__device__ __forceinline__ void mma_bf16(float* c, const uint32_t* a, const uint32_t* b) {
    asm volatile(
        "mma.sync.aligned.m16n8k16.row.col.f32.bf16.bf16.f32 "
        "{%0,%1,%2,%3}, {%4,%5,%6,%7}, {%8,%9}, {%0,%1,%2,%3};"
        : "+f"(c[0]), "+f"(c[1]), "+f"(c[2]), "+f"(c[3])
        : "r"(a[0]), "r"(a[1]), "r"(a[2]), "r"(a[3]), "r"(b[0]), "r"(b[1]));
}

// ---------------------------------------------------------------------------
// Kernel 1: warp-per-row L2-normalize + bf16 convert. Also resets g_done.
// ---------------------------------------------------------------------------
__global__ __launch_bounds__(256)
void k_norm_cvt(const float* __restrict__ f1, const float* __restrict__ f2) {
    if (blockIdx.x == 0 && blockIdx.y == 0 && threadIdx.x == 0) g_done = 0;

    const int wid = threadIdx.x >> 5;
    const int lane = threadIdx.x & 31;
    const int row = blockIdx.x * 8 + wid;
    const float* __restrict__ src = (blockIdx.y == 0) ? f1 : f2;
    __nv_bfloat16* __restrict__ dst = (blockIdx.y == 0) ? g_a : g_b;

    const float4* p4 = (const float4*)(src + (size_t)row * D);
    float4 v[6];
    float s = 0.0f;
    #pragma unroll
    for (int i = 0; i < 6; i++) {
        v[i] = p4[lane + i * 32];
        s += v[i].x * v[i].x + v[i].y * v[i].y + v[i].z * v[i].z + v[i].w * v[i].w;
    }
    #pragma unroll
    for (int off = 16; off > 0; off >>= 1) s += __shfl_xor_sync(0xFFFFFFFFu, s, off);
    const float inv = 1.0f / fmaxf(sqrtf(s), EPSN);

    __nv_bfloat162* q2 = (__nv_bfloat162*)(dst + (size_t)row * D);
    #pragma unroll
    for (int i = 0; i < 6; i++) {
        const int base = (lane + i * 32) * 2;
        q2[base + 0] = __floats2bfloat162_rn(v[i].x * inv, v[i].y * inv);
        q2[base + 1] = __floats2bfloat162_rn(v[i].z * inv, v[i].w * inv);
    }
}

// ---------------------------------------------------------------------------
// Kernel 2: bf16 mma.sync GEMM, 256x128 CTA tile, 512 threads (16 warps 4x4,
// warp tile 64x32). BK=64, 3-stage cp.async, XOR-8 swizzle, fused exp-sum.
// ---------------------------------------------------------------------------
__global__ __launch_bounds__(512, 1)
void k_gemm_fused() {
    extern __shared__ char smem[];
    const uint32_t sbase = smem_u32(smem);
    const int tid = threadIdx.x;
    const int wid = tid >> 5;
    const int lane = tid & 31;
    const int bx = blockIdx.x, by = blockIdx.y;
    const int bi = by * BM, bj = bx * BN;

    const int wy = wid >> 2;        // 0..3
    const int wx = wid & 3;         // 0..3
    const int m0 = wy * 64;
    const int n0 = wx * 32;

    // stage chunk c: A 256x64 (2048 x 16B) + B 128x64 (1024 x 16B) = 3072; 6/thread
    auto load_chunk = [&](int c, int s) {
        const int k0 = c * BK;
        const uint32_t st = sbase + s * STAGE_BYTES;
        #pragma unroll
        for (int i = 0; i < 6; i++) {
            const int idx = tid + i * 512;          // 0..3071
            const bool isB = idx >= 2048;
            const int id2 = isB ? (idx - 2048) : idx;
            const int row = id2 >> 3;
            const int ch  = id2 & 7;
            const uint32_t soff = (uint32_t)(row * 128 + ((ch ^ (row & 7)) << 4));
            const __nv_bfloat16* src = (isB ? g_b + (size_t)(bj + row) * D
                                            : g_a + (size_t)(bi + row) * D) + k0 + ch * 8;
            CP_ASYNC16(st + (isB ? A_BYTES : 0) + soff, src);
        }
        CP_COMMIT();
    };

    // ldmatrix lane-address precompute
    uint32_t aRB[4], aR7[4];
    #pragma unroll
    for (int mt = 0; mt < 4; mt++) {
        const int r = m0 + mt * 16 + (lane & 15);
        aRB[mt] = (uint32_t)(r * 128);
        aR7[mt] = (uint32_t)(r & 7);
    }
    uint32_t bRB[2], bR7[2];
    #pragma unroll
    for (int p = 0; p < 2; p++) {
        const int r = n0 + p * 16 + ((lane >> 4) << 3) + (lane & 7);
        bRB[p] = (uint32_t)(r * 128);
        bR7[p] = (uint32_t)(r & 7);
    }
    const uint32_t chA = (uint32_t)(lane >> 4);
    const uint32_t chB = (uint32_t)((lane >> 3) & 1);

    float acc[4][4][4];
    #pragma unroll
    for (int mt = 0; mt < 4; mt++)
        #pragma unroll
        for (int nt = 0; nt < 4; nt++)
            #pragma unroll
            for (int r = 0; r < 4; r++) acc[mt][nt][r] = 0.0f;

    load_chunk(0, 0);
    load_chunk(1, 1);

    for (int c = 0; c < NCH; c++) {
        CP_WAIT(1);
        __syncthreads();
        if (c + 2 < NCH) {
            load_chunk(c + 2, (c + 2) % 3);
        } else {
            CP_COMMIT();
        }

        const uint32_t sA = sbase + (c % 3) * STAGE_BYTES;
        const uint32_t sB = sA + A_BYTES;

        #pragma unroll
        for (int ks = 0; ks < 4; ks++) {
            uint32_t a[4][4];
            #pragma unroll
            for (int mt = 0; mt < 4; mt++) {
                const uint32_t ch = 2 * ks + chA;
                ldmx4(a[mt], sA + aRB[mt] + ((ch ^ aR7[mt]) << 4));
            }
            uint32_t b[4][2];
            #pragma unroll
            for (int p = 0; p < 2; p++) {
                uint32_t t[4];
                const uint32_t ch = 2 * ks + chB;
                ldmx4(t, sB + bRB[p] + ((ch ^ bR7[p]) << 4));
                b[2 * p][0] = t[0]; b[2 * p][1] = t[1];
                b[2 * p + 1][0] = t[2]; b[2 * p + 1][1] = t[3];
            }
            #pragma unroll
            for (int mt = 0; mt < 4; mt++)
                #pragma unroll
                for (int nt = 0; nt < 4; nt++)
                    mma_bf16(acc[mt][nt], a[mt], b[nt]);
        }
    }

    // ---------------- fused epilogue ----------------
    const int g = lane >> 2;
    const int tig = lane & 3;
    const int dOff = bj - bi;                       // diag when 0 or 128
    const bool diagBlk = (dOff == 0) || (dOff == BN);

    float rowsum[8];
    #pragma unroll
    for (int h = 0; h < 8; h++) rowsum[h] = 0.0f;

    #pragma unroll
    for (int mt = 0; mt < 4; mt++) {
        #pragma unroll
        for (int nt = 0; nt < 4; nt++) {
            const float v0 = acc[mt][nt][0] * TEMP_INV;
            const float v1 = acc[mt][nt][1] * TEMP_INV;
            const float v2 = acc[mt][nt][2] * TEMP_INV;
            const float v3 = acc[mt][nt][3] * TEMP_INV;
            rowsum[mt * 2 + 0] += __expf(v0 - 20.0f) + __expf(v1 - 20.0f);
            rowsum[mt * 2 + 1] += __expf(v2 - 20.0f) + __expf(v3 - 20.0f);
            if (diagBlk) {
                const int i0 = m0 + mt * 16 + g;     // local row
                const int i1 = i0 + 8;
                const int j0 = n0 + nt * 8 + tig * 2 + dOff;  // local row of diag match
                if (i0 == j0)     g_diag[bi + i0] = v0;
                if (i0 == j0 + 1) g_diag[bi + i0] = v1;
                if (i1 == j0)     g_diag[bi + i1] = v2;
                if (i1 == j0 + 1) g_diag[bi + i1] = v3;
            }
        }
    }
    #pragma unroll
    for (int h = 0; h < 8; h++) {
        rowsum[h] += __shfl_xor_sync(0xFFFFFFFFu, rowsum[h], 1);
        rowsum[h] += __shfl_xor_sync(0xFFFFFFFFu, rowsum[h], 2);
    }

    __syncthreads();
    float* part = (float*)smem;  // [256][4] = 4 KB
    if (tig == 0) {
        #pragma unroll
        for (int h = 0; h < 8; h++) {
            const int r = m0 + (h >> 1) * 16 + (h & 1) * 8 + g;
            part[r * 4 + wx] = rowsum[h];
        }
    }
    __syncthreads();
    if (tid < 256) {
        const float s = part[tid * 4 + 0] + part[tid * 4 + 1] +
                        part[tid * 4 + 2] + part[tid * 4 + 3];
        g_partial[(size_t)(bi + tid) * 32 + bx] = s;
    }
}

// ---------------------------------------------------------------------------
// Kernel 3: per-row loss + deterministic mean (last block reduces).
// ---------------------------------------------------------------------------
__global__ void k_rowloss_fin(float* __restrict__ out) {
    const int row = blockIdx.x * 128 + threadIdx.x;
    const float4* p = (const float4*)(g_partial + (size_t)row * 32);
    float s = 0.0f;
    #pragma unroll
    for (int i = 0; i < 8; i++) {
        float4 v = p[i];
        s += v.x + v.y + v.z + v.w;
    }
    g_rowloss[row] = logf(s) + 20.0f - g_diag[row];

    __threadfence();
    __shared__ bool isLast;
    if (threadIdx.x == 0) {
        isLast = (atomicAdd(&g_done, 1) == 31);
    }
    __syncthreads();
    if (!isLast) return;

    float t = 0.0f;
    const float4* rl = (const float4*)g_rowloss;
    #pragma unroll
    for (int i = 0; i < 8; i++) {
        float4 v = rl[threadIdx.x + i * 128];
        t += v.x + v.y + v.z + v.w;
    }
    __shared__ float sm[128];
    sm[threadIdx.x] = t;
    __syncthreads();
    #pragma unroll
    for (int off = 64; off > 0; off >>= 1) {
        if (threadIdx.x < off) sm[threadIdx.x] += sm[threadIdx.x + off];
        __syncthreads();
    }
    if (threadIdx.x == 0) out[0] = sm[0] / (float)N;
}

// ---------------------------------------------------------------------------
extern "C" void kernel_launch(void* const* d_in, const int* in_sizes, int n_in,
                              void* d_out, int out_size) {
    const float* f1 = (const float*)d_in[0];
    const float* f2 = (const float*)d_in[1];
    float* out = (float*)d_out;

    cudaFuncSetAttribute(k_gemm_fused, cudaFuncAttributeMaxDynamicSharedMemorySize, SMEM_DYN);

    k_norm_cvt<<<dim3(N / 8, 2), 256>>>(f1, f2);
    k_gemm_fused<<<dim3(N / BN, N / BM), 512, SMEM_DYN>>>();
    k_rowloss_fin<<<32, 128>>>(out);
}